// round 17
// baseline (speedup 1.0000x reference)
#include <cuda_runtime.h>
#include <cstdint>

#define NBOX   8192
#define CLS    81
#define NPAD   300
#define NWORDS (NBOX / 32)      // 256 words per mask row
#define NCH    (NBOX / 64)      // 128 scan chunks of 64 boxes
#define MAXK   8                // staged keep rows per chunk (overflow -> direct)

typedef unsigned long long u64;

// ------------------------- device scratch (static, no allocs) --------------
__device__ float4   g_selv[NBOX];     // decoded boxes (orig order)
__device__ u64      g_key[NBOX];      // composite sort keys
__device__ float4   g_sbox[NBOX];     // boxes in sorted order
__device__ float    g_sarea[NBOX];    // areas in sorted order
__device__ int      g_orig[NBOX];     // sorted pos -> original idx
__device__ unsigned g_masks[(size_t)NBOX * NWORDS]; // sorted-space IoU>0.5

// ------------------------- cp.async helpers --------------------------------
__device__ __forceinline__ void cp_async16(void* smem_dst, const void* gmem_src) {
    unsigned saddr = (unsigned)__cvta_generic_to_shared(smem_dst);
    asm volatile("cp.async.cg.shared.global [%0], [%1], 16;\n"
                 :: "r"(saddr), "l"(gmem_src));
}
__device__ __forceinline__ void cp_async8(void* smem_dst, const void* gmem_src) {
    unsigned saddr = (unsigned)__cvta_generic_to_shared(smem_dst);
    asm volatile("cp.async.ca.shared.global [%0], [%1], 8;\n"
                 :: "r"(saddr), "l"(gmem_src));
}
__device__ __forceinline__ void cp_commit() {
    asm volatile("cp.async.commit_group;\n" ::);
}
__device__ __forceinline__ void cp_wait1() {
    asm volatile("cp.async.wait_group 1;\n" ::: "memory");
}
__device__ __forceinline__ void cp_wait0() {
    asm volatile("cp.async.wait_group 0;\n" ::: "memory");
}

// ---------------------------------------------------------------------------
// Kernel 1: per-row argmax / max + bbox decode + sort-key build. 1 warp/row.
// ---------------------------------------------------------------------------
__global__ void decode_kernel(const float* __restrict__ meta,
                              const float* __restrict__ deltas,
                              const float* __restrict__ proposals,
                              const float* __restrict__ scores) {
    int row  = (int)((blockIdx.x * blockDim.x + threadIdx.x) >> 5);
    int lane = threadIdx.x & 31;
    if (row >= NBOX) return;

    const float* srow = scores + (size_t)row * CLS;
    float best = -1.0f;
    int   bidx = 0x7FFFFFFF;
    float ms   = -1.0f;
    for (int j = lane; j < CLS; j += 32) {
        float v = srow[j];
        if (v > best) { best = v; bidx = j; }
        if (j >= 1) ms = fmaxf(ms, v);
    }
    #pragma unroll
    for (int off = 16; off; off >>= 1) {
        float ov = __shfl_down_sync(0xffffffffu, best, off);
        int   oi = __shfl_down_sync(0xffffffffu, bidx, off);
        float om = __shfl_down_sync(0xffffffffu, ms,   off);
        if (ov > best || (ov == best && oi < bidx)) { best = ov; bidx = oi; }
        ms = fmaxf(ms, om);
    }

    if (lane == 0) {
        float scale = meta[2];
        const float* p = proposals + (size_t)row * 4;
        float x1 = p[0] / scale, y1 = p[1] / scale;
        float x2 = p[2] / scale, y2 = p[3] / scale;
        float w  = x2 - x1 + 1.0f, h = y2 - y1 + 1.0f;
        float cx = x1 + 0.5f * w,  cy = y1 + 0.5f * h;

        const float* d = deltas + (size_t)row * (4 * CLS) + 4 * bidx;
        float pcx = d[0] * w + cx;
        float pcy = d[1] * h + cy;
        float pw  = expf(d[2]) * w;
        float ph  = expf(d[3]) * h;

        float W1 = meta[1] - 1.0f;
        float H1 = meta[0] - 1.0f;
        float ox1 = fminf(fmaxf(pcx - 0.5f * pw, 0.0f), W1);
        float oy1 = fminf(fmaxf(pcy - 0.5f * ph, 0.0f), H1);
        float ox2 = fminf(fmaxf(pcx + 0.5f * pw, 0.0f), W1);
        float oy2 = fminf(fmaxf(pcy + 0.5f * ph, 0.0f), H1);

        g_selv[row] = make_float4(ox1, oy1, ox2, oy2);
        unsigned int sb = __float_as_uint(ms);   // scores >= 0 -> monotonic bits
        g_key[row] = ((u64)sb << 13) | (u64)(8191 - row);   // all keys distinct
    }
}

// ---------------------------------------------------------------------------
// Kernel 2: rank-by-counting + scatter into sorted order. 256 blocks.
// ---------------------------------------------------------------------------
__global__ void __launch_bounds__(256)
rank_kernel() {
    extern __shared__ u64 keys[];   // 64 KB
    const int tid = threadIdx.x;
    for (int i = tid; i < NBOX; i += 256) keys[i] = g_key[i];
    __syncthreads();

    const int warp = tid >> 5, lane = tid & 31;
    const int row0 = blockIdx.x * 32 + warp * 4;

    u64 rk0 = keys[row0 + 0];
    u64 rk1 = keys[row0 + 1];
    u64 rk2 = keys[row0 + 2];
    u64 rk3 = keys[row0 + 3];
    int c0 = 0, c1 = 0, c2 = 0, c3 = 0;

    #pragma unroll 4
    for (int c = lane; c < NBOX; c += 32) {
        u64 kc = keys[c];
        c0 += (kc > rk0);
        c1 += (kc > rk1);
        c2 += (kc > rk2);
        c3 += (kc > rk3);
    }
    #pragma unroll
    for (int off = 16; off; off >>= 1) {
        c0 += __shfl_down_sync(0xffffffffu, c0, off);
        c1 += __shfl_down_sync(0xffffffffu, c1, off);
        c2 += __shfl_down_sync(0xffffffffu, c2, off);
        c3 += __shfl_down_sync(0xffffffffu, c3, off);
    }
    if (lane == 0) {
        int rr[4] = {c0, c1, c2, c3};
        #pragma unroll
        for (int q = 0; q < 4; q++) {
            int i = row0 + q, r = rr[q];
            float4 b = g_selv[i];
            g_sbox[r]  = b;
            g_sarea[r] = fmaxf(b.z - b.x, 0.0f) * fmaxf(b.w - b.y, 0.0f);
            g_orig[r]  = i;
        }
    }
}

// ---------------------------------------------------------------------------
// Kernel 3: sorted-space IoU>0.5 bitmask, upper-triangle tiles only (1152).
// ---------------------------------------------------------------------------
__constant__ int c_prefix[9] = {0, 256, 480, 672, 832, 960, 1056, 1120, 1152};

__global__ void __launch_bounds__(256)
mask_kernel() {
    __shared__ float4 rbs[32];
    __shared__ float  ras[32];
    __shared__ float4 cbT[32 * 33];
    __shared__ float  caT[32 * 33];

    const int t = blockIdx.x;
    int g = 0;
    #pragma unroll
    for (int h = 1; h < 8; h++) g += (t >= c_prefix[h]);
    const int tp   = t - c_prefix[g];
    const int span = 8 - g;
    const int r    = tp / span;
    const int rb   = g * 32 + r;
    const int cb   = g + (tp - r * span);

    const int rowbase = rb * 32;
    const int colbase = cb * 1024;
    const int tid = threadIdx.x;

    if (tid < 32) {
        rbs[tid] = g_sbox[rowbase + tid];
        ras[tid] = g_sarea[rowbase + tid];
    }
    for (int jj = tid; jj < 1024; jj += 256) {
        int w = jj >> 5, bb = jj & 31;
        cbT[bb * 33 + w] = g_sbox[colbase + jj];
        caT[bb * 33 + w] = g_sarea[colbase + jj];
    }
    __syncthreads();

    const int r0 = tid >> 5;
    const int w  = tid & 31;
    float4 bi[4];
    float  si[4];
    #pragma unroll
    for (int k = 0; k < 4; k++) {
        bi[k] = rbs[r0 + 8 * k];
        si[k] = ras[r0 + 8 * k] + 1e-8f;
    }
    unsigned bits0 = 0, bits1 = 0, bits2 = 0, bits3 = 0;

    #pragma unroll
    for (int b = 0; b < 32; b++) {
        float4 bj = cbT[b * 33 + w];
        float  aj = caT[b * 33 + w];
        #pragma unroll
        for (int k = 0; k < 4; k++) {
            float xx1 = fmaxf(bi[k].x, bj.x), yy1 = fmaxf(bi[k].y, bj.y);
            float xx2 = fminf(bi[k].z, bj.z), yy2 = fminf(bi[k].w, bj.w);
            float iw  = fmaxf(xx2 - xx1, 0.0f);
            float ih  = fmaxf(yy2 - yy1, 0.0f);
            float inter = iw * ih;
            unsigned p = (3.0f * inter > si[k] + aj) ? (1u << b) : 0u;
            if (k == 0) bits0 |= p;
            else if (k == 1) bits1 |= p;
            else if (k == 2) bits2 |= p;
            else bits3 |= p;
        }
    }
    size_t base = (size_t)rowbase * NWORDS + (size_t)cb * 32 + w;
    g_masks[base + (size_t)(r0 +  0) * NWORDS] = bits0;
    g_masks[base + (size_t)(r0 +  8) * NWORDS] = bits1;
    g_masks[base + (size_t)(r0 + 16) * NWORDS] = bits2;
    g_masks[base + (size_t)(r0 + 24) * NWORDS] = bits3;
}

// ---------------------------------------------------------------------------
// Kernel 4: SINGLE-WARP cp.async greedy scan (no __syncthreads in loop).
//  iter c: wait_group 1 (retires group c-2) -> apply staged keeps(c-2) ->
//          resolve chunk c (sup lag c-2; supfix = n1acc(c-1) only) ->
//          issue gathers for keeps(c) + operands chunk c+2 -> commit.
//  All lanes run uniformly; lane owns sup words lane+32q and stage bytes
//  [32*lane, 32*lane+32). Warps 1-7 sleep until the output epilogue.
// ---------------------------------------------------------------------------
__global__ void __launch_bounds__(256)
scan_kernel(const float* __restrict__ scores, float* __restrict__ out) {
    __shared__ unsigned sup_s[NWORDS];            // 1 KB
    __shared__ u64      conf_s[4][64];            // 2 KB
    __shared__ u64      n1_s[4][64];              // 2 KB
    __shared__ unsigned stage[4][MAXK][NWORDS];   // 32 KB
    __shared__ int      s_keep[NPAD];
    __shared__ int      s_nk;

    const int tid  = threadIdx.x;
    const int lane = tid & 31;
    for (int i = tid; i < NWORDS; i += 256) sup_s[i] = 0u;
    __syncthreads();

    if (tid < 32) {
        const u64* m64 = (const u64*)g_masks;     // row stride = 128 u64

        // prologue: operands for chunks 0 and 1 (conf word c, n1 word c+1)
        for (int t = lane; t < 128; t += 32) {
            int row = t & 63, f = t >> 6;         // f: 0=conf, 1=n1
            u64 v0 = __ldg(m64 + (size_t)row        * 128 + 0 + f);
            u64 v1 = __ldg(m64 + (size_t)(64 + row) * 128 + 1 + f);
            if (f == 0) { conf_s[0][row] = v0; conf_s[1][row] = v1; }
            else        { n1_s[0][row]   = v0; n1_s[1][row]   = v1; }
        }
        __syncwarp();
        cp_commit();  cp_commit();                // empty groups (alignment)

        u64 supfix = 0ull;
        u64 kb1 = 0ull, kb2 = 0ull;               // keeps(c-1), keeps(c-2)
        int kept = 0;

        for (int c = 0; c < NCH; c++) {
            cp_wait1();                           // retires group c-2
            __syncwarp();

            // ---- apply staged keeps(c-2) to owned sup words ----
            if (kb2) {
                const int slot_a = (c - 2) & 3;
                unsigned acc[8];
                #pragma unroll
                for (int q = 0; q < 8; q++) acc[q] = 0u;
                u64 ka = kb2; int s = 0;
                while (ka) {
                    int l = __ffsll((long long)ka) - 1; ka &= ka - 1;
                    if (s < MAXK) {
                        #pragma unroll
                        for (int q = 0; q < 8; q++)
                            acc[q] |= stage[slot_a][s][lane + 32 * q];
                    } else {                       // rare overflow fallback
                        const unsigned* row =
                            g_masks + (size_t)(64 * (c - 2) + l) * NWORDS;
                        #pragma unroll
                        for (int q = 0; q < 8; q++)
                            acc[q] |= __ldg(row + lane + 32 * q);
                    }
                    s++;
                }
                #pragma unroll
                for (int q = 0; q < 8; q++)
                    if (acc[q]) sup_s[lane + 32 * q] |= acc[q];
                __syncwarp();
            }

            // ---- resolve chunk c (uniform across lanes) ----
            const int slot = c & 3;
            u64 sup64 = *(const u64*)&sup_s[2 * c];
            u64 am = ~(sup64 | supfix);
            u64 keepm = 0ull, n1acc = 0ull;
            while (am) {
                int l = __ffsll((long long)am) - 1;
                keepm |= 1ull << l;
                n1acc |= n1_s[slot][l];
                am &= ~conf_s[slot][l];
                am &= ~(1ull << l);
                if (kept < NPAD) {
                    if (lane == 0) s_keep[kept] = c * 64 + l;
                    kept++;
                }
            }
            supfix = n1acc;
            if (kept >= NPAD) break;

            // ---- issue gathers for keeps(c): lane covers words 8l..8l+7 ----
            u64 km = keepm; int s = 0;
            while (km && s < MAXK) {
                int l = __ffsll((long long)km) - 1; km &= km - 1;
                const unsigned* row =
                    g_masks + (size_t)(64 * c + l) * NWORDS;
                cp_async16(&stage[slot][s][8 * lane],     row + 8 * lane);
                cp_async16(&stage[slot][s][8 * lane + 4], row + 8 * lane + 4);
                s++;
            }

            // ---- operand prefetch for chunk c+2 ----
            const int cf = c + 2;
            if (cf < NCH) {
                for (int t = lane; t < 128; t += 32) {
                    int row = t & 63, f = t >> 6;
                    int wi = cf + f; if (wi > 127) wi = 127;   // tail clamp
                    if (f == 0)
                        cp_async8(&conf_s[cf & 3][row],
                                  m64 + (size_t)(64 * cf + row) * 128 + wi);
                    else
                        cp_async8(&n1_s[cf & 3][row],
                                  m64 + (size_t)(64 * cf + row) * 128 + wi);
                }
            }
            cp_commit();                          // one group per iteration
            kb2 = kb1; kb1 = keepm;
        }
        cp_wait0();
        if (lane == 0) s_nk = kept;
    }
    __syncthreads();                              // warps 1-7 wake here
    const int nk = s_nk;

    // ---- outputs: boxes (300*4) then scores (300*81); zero invalid rows ----
    for (int idx = tid; idx < NPAD * 4; idx += 256) {
        int r = idx >> 2, cc = idx & 3;
        float v = 0.0f;
        if (r < nk) {
            float4 b = g_sbox[s_keep[r]];
            v = (cc == 0) ? b.x : (cc == 1) ? b.y : (cc == 2) ? b.z : b.w;
        }
        out[idx] = v;
    }
    for (int idx = tid; idx < NPAD * CLS; idx += 256) {
        int r = idx / CLS, cc = idx - r * CLS;
        float v = 0.0f;
        if (r < nk)
            v = scores[(size_t)g_orig[s_keep[r]] * CLS + cc];
        out[NPAD * 4 + idx] = v;
    }
}

// ---------------------------------------------------------------------------
extern "C" void kernel_launch(void* const* d_in, const int* in_sizes, int n_in,
                              void* d_out, int out_size) {
    const float* meta      = (const float*)d_in[0];
    const float* deltas    = (const float*)d_in[1];
    const float* proposals = (const float*)d_in[2];
    const float* scores    = (const float*)d_in[3];
    float* out = (float*)d_out;

    decode_kernel<<<NBOX / 8, 256>>>(meta, deltas, proposals, scores);

    cudaFuncSetAttribute(rank_kernel,
                         cudaFuncAttributeMaxDynamicSharedMemorySize, 65536);
    rank_kernel<<<256, 256, 65536>>>();

    mask_kernel<<<1152, 256>>>();

    scan_kernel<<<1, 256>>>(scores, out);
}